// round 11
// baseline (speedup 1.0000x reference)
#include <cuda_runtime.h>

// pred/target: (2,2,128,128,128) fp32 contiguous. idx = bc*2^21 + d*2^14 + h*2^7 + w
#define NTOT 8388608
#define BC_STRIDE 2097152
#define D_STRIDE  16384

// After W+H passes: packed u32 per voxel = predEDT2 | targEDT2<<16.
// Real values <= 32258; sentinel = 0xC000 (49152) so that +rr (<=16129) never
// carries into the high half and never beats a real candidate (<=48387).
__device__ unsigned int g_pt[NTOT];
__device__ double g_acc;
__device__ int g_count;

// ---------------------------------------------------------------------------
// Fused pass1 (W axis, two-sweep on byte-packed distances, BOTH tensors) +
// pass2 (H axis, pruned exact scan, squares via IMAD on the fly).
// One (bc,d) slab 128x128 per block; grid=512, block=256; 33KB static smem.
// ---------------------------------------------------------------------------
__global__ void __launch_bounds__(256) k_pass12(const float* __restrict__ pred,
                                                const float* __restrict__ target) {
    __shared__ unsigned short md[128][130];   // byte-packed: pred | targ<<8
    const int tid = threadIdx.x;
    const long base = (long)blockIdx.x * 16384;

    if (blockIdx.x == 0 && tid == 0) g_acc = 0.0;

    // mask load, both tensors: byte = 0 (background) / 1 (foreground)
    const float4* p4 = (const float4*)(pred + base);
    const float4* t4 = (const float4*)(target + base);
    #pragma unroll
    for (int it = 0; it < 16; it++) {
        int idx = it * 256 + tid;            // 0..4095 float4
        float4 p = p4[idx], t = t4[idx];
        int r  = idx >> 5;
        int w4 = (idx & 31) * 4;
        unsigned u0 = (p.x >= 0.5f ? 1u : 0u) | (t.x >= 0.5f ? 0x100u : 0u);
        unsigned u1 = (p.y >= 0.5f ? 1u : 0u) | (t.y >= 0.5f ? 0x100u : 0u);
        unsigned u2 = (p.z >= 0.5f ? 1u : 0u) | (t.z >= 0.5f ? 0x100u : 0u);
        unsigned u3 = (p.w >= 0.5f ? 1u : 0u) | (t.w >= 0.5f ? 0x100u : 0u);
        *(unsigned*)&md[r][w4]     = u0 | (u1 << 16);
        *(unsigned*)&md[r][w4 + 2] = u2 | (u3 << 16);
    }
    __syncthreads();

    // pass1: forward/backward sweeps along w, thread = row. dist 255 = "no bg".
    if (tid < 128) {
        unsigned short* row = md[tid];
        int dp = 255, dt = 255;
        #pragma unroll 4
        for (int w = 0; w < 128; w++) {
            int m = row[w];
            dp = (m & 0xff)   ? min(dp + 1, 255) : 0;
            dt = (m & 0xff00) ? min(dt + 1, 255) : 0;
            row[w] = (unsigned short)(dp | (dt << 8));
        }
        int ep = 255, et = 255;
        #pragma unroll 4
        for (int w = 127; w >= 0; w--) {
            int v = row[w];
            int vp = v & 0xff, vt = v >> 8;
            ep = vp ? min(ep + 1, 255) : 0;
            et = vt ? min(et + 1, 255) : 0;
            vp = min(vp, ep);
            vt = min(vt, et);
            row[w] = (unsigned short)(vp | (vt << 8));
        }
    }
    __syncthreads();

    // pass2: out[x][w] = min_y (d(y)^2 + (x-y)^2), pruned outward scan, both
    // tensors per lane. warp = output row x, lanes = 32 consecutive w.
    const int warp = tid >> 5, lane = tid & 31;
    for (int i = 0; i < 16; i++) {
        int x = warp + 8 * i;
        #pragma unroll
        for (int wg = 0; wg < 4; wg++) {
            int w = wg * 32 + lane;
            int v0 = md[x][w];
            int a0 = v0 & 0xff, c0 = v0 >> 8;
            int bp = a0 * a0;                // 255^2 = 65025 acts as +inf
            int bt = c0 * c0;
            int rr = 1;
            for (int r = 1; r < 128; r++) {
                if (__all_sync(0xffffffffu, rr >= max(bp, bt))) break;
                int lo = x - r, hi = x + r;
                if (lo >= 0) {
                    int v = md[lo][w];
                    int a = v & 0xff, c = v >> 8;
                    bp = min(bp, a * a + rr);
                    bt = min(bt, c * c + rr);
                }
                if (hi < 128) {
                    int v = md[hi][w];
                    int a = v & 0xff, c = v >> 8;
                    bp = min(bp, a * a + rr);
                    bt = min(bt, c * c + rr);
                }
                rr += 2 * r + 1;
            }
            bp = (bp > 32258) ? 49152 : bp;  // sentinel 0xC000: carry-safe
            bt = (bt > 32258) ? 49152 : bt;
            g_pt[base + x * 128 + w] = (unsigned)bp | ((unsigned)bt << 16);
        }
    }
}

// ---------------------------------------------------------------------------
// Pass3 (D axis, packed pruned scan) fused with loss + final output.
// Block = 512, tile = fixed (bc,h), w0..w0+63, all 128 d. grid=(2,128,4).
// ---------------------------------------------------------------------------
__global__ void __launch_bounds__(512) k_pass3(const float* __restrict__ pred,
                                               const float* __restrict__ target,
                                               const int* __restrict__ is_avg,
                                               float* __restrict__ out) {
    __shared__ unsigned int gpt[128][66];
    __shared__ double sd[16];

    const int tid = threadIdx.x;
    const int w0 = blockIdx.x * 64;
    const int h  = blockIdx.y;
    const int bc = blockIdx.z;
    const long base = (long)bc * BC_STRIDE + (long)h * 128 + w0;

    // stage packed tile: 128 rows x 32 uint2 = 4096 uint2 (FIX: it < 8)
    #pragma unroll
    for (int it = 0; it < 8; it++) {
        int idx = it * 512 + tid;            // 0..4095 uint2
        int d = idx >> 5, w2 = (idx & 31) * 2;
        long a = base + (long)d * D_STRIDE + w2;
        *(uint2*)&gpt[d][w2] = *(const uint2*)&g_pt[a];
    }
    __syncthreads();

    // packed pruned scan along d + inline loss
    const int warp = tid >> 5, lane = tid & 31;
    double acc = 0.0;
    for (int i = 0; i < 8; i++) {
        int x = warp + 16 * i;
        #pragma unroll
        for (int wg = 0; wg < 2; wg++) {
            int w = wg * 32 + lane;
            unsigned b = gpt[x][w];
            int rr = 1;
            unsigned rrp = 0x00010001u;
            for (int r = 1; r < 128; r++) {
                unsigned bmax = max(b >> 16, b & 0xffffu);
                if (__all_sync(0xffffffffu, (unsigned)rr >= bmax)) break;
                int lo = x - r, hi = x + r;
                if (lo >= 0)  b = __vminu2(b, gpt[lo][w] + rrp);
                if (hi < 128) b = __vminu2(b, gpt[hi][w] + rrp);
                rr += 2 * r + 1;
                rrp = (unsigned)rr * 0x00010001u;
            }
            long a = base + (long)x * D_STRIDE + w;
            float e = pred[a] - target[a];
            acc += (double)(e * e * (float)((b & 0xffffu) + (b >> 16)));
        }
    }

    #pragma unroll
    for (int s = 16; s > 0; s >>= 1)
        acc += __shfl_down_sync(0xffffffffu, acc, s);
    if (lane == 0) sd[warp] = acc;
    __syncthreads();
    if (warp == 0) {
        double v = (lane < 16) ? sd[lane] : 0.0;
        #pragma unroll
        for (int s = 8; s > 0; s >>= 1)
            v += __shfl_down_sync(0xffffffffu, v, s);
        if (lane == 0) atomicAdd(&g_acc, v);
    }
    __syncthreads();

    // last block computes the final scalar (folds old k_final)
    if (tid == 0) {
        __threadfence();
        int old = atomicAdd(&g_count, 1);
        if (old == 2 * 128 * 4 - 1) {
            double m = g_acc / (double)NTOT;
            if (*is_avg == 0) m *= 2.0;      // * pred.shape[0]
            out[0] = (float)m;
            g_count = 0;                      // reset for next graph replay
        }
    }
}

extern "C" void kernel_launch(void* const* d_in, const int* in_sizes, int n_in,
                              void* d_out, int out_size) {
    const float* pred   = (const float*)d_in[0];
    const float* target = (const float*)d_in[1];
    const int*   is_avg = (const int*)d_in[2];
    float* out = (float*)d_out;

    k_pass12<<<512, 256>>>(pred, target);
    k_pass3<<<dim3(2, 128, 4), 512>>>(pred, target, is_avg, out);
}